// round 6
// baseline (speedup 1.0000x reference)
#include <cuda_runtime.h>
#include <stdint.h>

#define IN_DIM 16384
#define HID    128
#define ALLN   200000
#define NODES  2000
#define SEG    100
#define NSAMP  128

// Output layout (float32):
//   [0, 256000)            positions[s][n]  (s-major)
//   [256000, 256128)       log_softmax[s]
//   [256128, 456128)       scores[0..200000)
#define OFF_LOGSM (NSAMP * NODES)
#define OFF_SCORES (NSAMP * NODES + NSAMP)

// ---------------- device scratch (no allocation allowed) ----------------
__device__ float g_hpart[128][HID];  // per-block W1 partials (overwritten each run)
__device__ float g_hs[HID];          // final tanh(x@W1 + b1)

// ---------------- XLA f32 tanh (Eigen-style rational approx) ----------------
__device__ __forceinline__ float tanh_xla(float x) {
    float ax = fabsf(x);
    if (ax < 0.0004f) return x;
    float xc = fminf(fmaxf(x, -9.0f), 9.0f);
    float x2 = xc * xc;
    float np = fmaf(x2, -2.76076847742355e-16f, 2.00018790482477e-13f);
    np = fmaf(x2, np, -8.60467152213735e-11f);
    np = fmaf(x2, np, 5.12229709037114e-08f);
    np = fmaf(x2, np, 1.48572235717979e-05f);
    np = fmaf(x2, np, 6.37261928875436e-04f);
    np = fmaf(x2, np, 4.89352455891786e-03f);
    np = np * xc;
    float dp = fmaf(x2, 1.19825839466702e-06f, 1.18534705686654e-04f);
    dp = fmaf(x2, dp, 2.26843463243900e-03f);
    dp = fmaf(x2, dp, 4.89352518554385e-03f);
    return np / dp;
}

// ---------------- threefry2x32, key=(0,42), counts=(0, i) --------------------
// Partitionable JAX scheme, 32-bit: bits[i] = out0 ^ out1.
__device__ __forceinline__ unsigned tf_xor(unsigned ctr) {
    const unsigned K0 = 0u;
    const unsigned K1 = 42u;
    const unsigned K2 = 0u ^ 42u ^ 0x1BD11BDAu;
    unsigned x0 = 0u + K0;
    unsigned x1 = ctr + K1;
#define TFR(r) { x0 += x1; x1 = __funnelshift_l(x1, x1, (r)); x1 ^= x0; }
    TFR(13) TFR(15) TFR(26) TFR(6)
    x0 += K1; x1 += K2 + 1u;
    TFR(17) TFR(29) TFR(16) TFR(24)
    x0 += K2; x1 += K0 + 2u;
    TFR(13) TFR(15) TFR(26) TFR(6)
    x0 += K0; x1 += K1 + 3u;
    TFR(17) TFR(29) TFR(16) TFR(24)
    x0 += K1; x1 += K2 + 4u;
    TFR(13) TFR(15) TFR(26) TFR(6)
    x0 += K2; x1 += K0 + 5u;
#undef TFR
    return x0 ^ x1;
}

// Exact JAX gumbel+score value for flat index ctr (used only to break near-ties)
__device__ __forceinline__ float precise_v(unsigned ctr, float rowk) {
    unsigned b = tf_xor(ctr);
    float f = __uint_as_float((b >> 9) | 0x3f800000u) - 1.0f;
    float u = fmaxf(f, 1.17549435e-38f);
    return -logf(-logf(u)) + rowk;
}

// ---------------- K1: atomic-free partials of x @ W1 -------------------------
// 128 blocks x 256 threads; block b covers input rows [b*128, b*128+128)
__global__ void k_h_partial(const float* __restrict__ x, const float* __restrict__ W1) {
    __shared__ float sm[256];
    int t = threadIdx.x;
    int j = t & 127;
    int half = t >> 7;
    int i0 = blockIdx.x * 128 + half * 64;
    float acc = 0.0f;
#pragma unroll 8
    for (int ii = 0; ii < 64; ii++) {
        int i = i0 + ii;
        acc = fmaf(x[i], W1[i * HID + j], acc);
    }
    sm[t] = acc;
    __syncthreads();
    if (t < 128) g_hpart[blockIdx.x][j] = sm[t] + sm[t + 128];
}

// ---------------- K2: reduce partials -> hs; zero log_softmax ----------------
__global__ void k_hsum(const float* __restrict__ b1, float* __restrict__ out) {
    int t = threadIdx.x;  // 128 threads
    float s = b1[t];
#pragma unroll 8
    for (int b = 0; b < 128; b++) s += g_hpart[b][t];
    g_hs[t] = tanh_xla(s);
    out[OFF_LOGSM + t] = 0.0f;
}

// ---------------- K3 fused: scores + rowstats + gumbel sampling --------------
// block = node n (2000 blocks x 128 threads); thread t = sample s in sampling phase
__global__ void __launch_bounds__(128) k_fused(const float* __restrict__ W2,
                                               const float* __restrict__ b2,
                                               float* __restrict__ out) {
    __shared__ float hs[HID];
    __shared__ float srow[SEG];
    __shared__ float sexp[SEG];   // exp(-srow[k]) for fast argmin metric
    __shared__ float red[8];
    __shared__ float sstat[2];    // rowmax, log(sumexp)
    const int n = blockIdx.x;
    const int t = threadIdx.x;
    const float NEGINF = -__int_as_float(0x7f800000);

    hs[t] = g_hs[t];
    __syncthreads();

    // --- scores for this node's 100 columns (coalesced over t) ---
    if (t < SEG) {
        int col = n * SEG + t;
        float acc = b2[col];
#pragma unroll 8
        for (int k = 0; k < HID; k++)
            acc = fmaf(hs[k], W2[(size_t)k * ALLN + col], acc);
        float sc = 10.0f * tanh_xla(acc);
        srow[t] = sc;
        sexp[t] = expf(-sc);
        out[OFF_SCORES + col] = sc;
    }
    __syncthreads();

    // --- in-block rowmax ---
    float v = (t < SEG) ? srow[t] : NEGINF;
#pragma unroll
    for (int off = 16; off > 0; off >>= 1)
        v = fmaxf(v, __shfl_xor_sync(0xffffffffu, v, off));
    if ((t & 31) == 0) red[t >> 5] = v;
    __syncthreads();
    if (t == 0) sstat[0] = fmaxf(fmaxf(red[0], red[1]), fmaxf(red[2], red[3]));
    __syncthreads();

    // --- in-block log(sum(exp(x - max))) ---
    float e = (t < SEG) ? expf(srow[t] - sstat[0]) : 0.0f;
#pragma unroll
    for (int off = 16; off > 0; off >>= 1)
        e += __shfl_xor_sync(0xffffffffu, e, off);
    if ((t & 31) == 0) red[4 + (t >> 5)] = e;
    __syncthreads();
    if (t == 0) sstat[1] = logf((red[4] + red[5]) + (red[6] + red[7]));
    __syncthreads();

    // --- sampling: thread t = sample s ---
    // argmax_k (gumbel_k + row_k) == argmin_k (-log u_k) * exp(-row_k)
    // Branchless top-3 on packed keys: key = (float_bits(m) & ~127) | k.
    // m > 0 always, so float bits are order-monotone; low 7 bits break quantized
    // ties toward smaller k.
    unsigned base = (unsigned)t * (unsigned)(NODES * SEG) + (unsigned)n * (unsigned)SEG;
    unsigned ka = 0xFFFFFFFFu, kb = 0xFFFFFFFFu, kc = 0xFFFFFFFFu;
#pragma unroll 4
    for (int k = 0; k < SEG; k++) {
        unsigned b = tf_xor(base + (unsigned)k);
        float f = __uint_as_float((b >> 9) | 0x3f800000u) - 1.0f;
        float u = fmaxf(f, 1.17549435e-38f);
        float nl = -logf(u);
        float m = nl * sexp[k];
        unsigned kk = (__float_as_uint(m) & 0xFFFFFF80u) | (unsigned)k;
        unsigned lo = umin(kk, ka); unsigned hi = umax(kk, ka); ka = lo;
        unsigned lo2 = umin(hi, kb); unsigned hi2 = umax(hi, kb); kb = lo2;
        kc = umin(hi2, kc);
    }

    int bk;
    if ((kb >> 7) - (ka >> 7) >= 3u) {
        // quantized gap >= 3 * 2^-16 relative: winner certain without recheck
        bk = (int)(ka & 127u);
    } else {
        // near-tie: resolve top-3 with the exact JAX expression (tie -> smaller k)
        int i1 = (int)(ka & 127u), i2 = (int)(kb & 127u), i3 = (int)(kc & 127u);
        float v1 = precise_v(base + (unsigned)i1, srow[i1]);
        float v2 = precise_v(base + (unsigned)i2, srow[i2]);
        float v3 = precise_v(base + (unsigned)i3, srow[i3]);
        bk = i1; float bv = v1;
        if (v2 > bv || (v2 == bv && i2 < bk)) { bv = v2; bk = i2; }
        if (v3 > bv || (v3 == bv && i3 < bk)) { bv = v3; bk = i3; }
    }

    out[t * NODES + n] = (float)bk;
    float lp = (srow[bk] - sstat[0]) - sstat[1];
    atomicAdd(&out[OFF_LOGSM + t], lp);
}

// ---------------- launch ----------------
extern "C" void kernel_launch(void* const* d_in, const int* in_sizes, int n_in,
                              void* d_out, int out_size) {
    const float* x  = (const float*)d_in[0];
    const float* W1 = (const float*)d_in[1];
    const float* b1 = (const float*)d_in[2];
    const float* W2 = (const float*)d_in[3];
    const float* b2 = (const float*)d_in[4];
    float* out = (float*)d_out;

    k_h_partial<<<IN_DIM / 128, 256>>>(x, W1);
    k_hsum<<<1, 128>>>(b1, out);
    k_fused<<<NODES, 128>>>(W2, b2, out);
}

// round 7
// speedup vs baseline: 1.0865x; 1.0865x over previous
#include <cuda_runtime.h>
#include <stdint.h>

#define IN_DIM 16384
#define HID    128
#define ALLN   200000
#define NODES  2000
#define SEG    100
#define NSAMP  128

// Output layout (float32):
//   [0, 256000)            positions[s][n]  (s-major)
//   [256000, 256128)       log_softmax[s]
//   [256128, 456128)       scores[0..200000)
#define OFF_LOGSM (NSAMP * NODES)
#define OFF_SCORES (NSAMP * NODES + NSAMP)

#define NPART 512

// ---------------- device scratch (no allocation allowed) ----------------
__device__ float g_hpart[NPART][HID];
__device__ float g_hs[HID];

// ---------------- XLA f32 tanh (Eigen-style rational approx) ----------------
__device__ __forceinline__ float tanh_xla(float x) {
    float ax = fabsf(x);
    if (ax < 0.0004f) return x;
    float xc = fminf(fmaxf(x, -9.0f), 9.0f);
    float x2 = xc * xc;
    float np = fmaf(x2, -2.76076847742355e-16f, 2.00018790482477e-13f);
    np = fmaf(x2, np, -8.60467152213735e-11f);
    np = fmaf(x2, np, 5.12229709037114e-08f);
    np = fmaf(x2, np, 1.48572235717979e-05f);
    np = fmaf(x2, np, 6.37261928875436e-04f);
    np = fmaf(x2, np, 4.89352455891786e-03f);
    np = np * xc;
    float dp = fmaf(x2, 1.19825839466702e-06f, 1.18534705686654e-04f);
    dp = fmaf(x2, dp, 2.26843463243900e-03f);
    dp = fmaf(x2, dp, 4.89352518554385e-03f);
    return np / dp;
}

// ---------------- threefry2x32, key=(0,42), counts=(0, i) --------------------
// Partitionable JAX scheme, 32-bit: bits[i] = out0 ^ out1.
__device__ __forceinline__ unsigned tf_xor(unsigned ctr) {
    const unsigned K0 = 0u;
    const unsigned K1 = 42u;
    const unsigned K2 = 0u ^ 42u ^ 0x1BD11BDAu;
    unsigned x0 = 0u + K0;
    unsigned x1 = ctr + K1;
#define TFR(r) { x0 += x1; x1 = __funnelshift_l(x1, x1, (r)); x1 ^= x0; }
    TFR(13) TFR(15) TFR(26) TFR(6)
    x0 += K1; x1 += K2 + 1u;
    TFR(17) TFR(29) TFR(16) TFR(24)
    x0 += K2; x1 += K0 + 2u;
    TFR(13) TFR(15) TFR(26) TFR(6)
    x0 += K0; x1 += K1 + 3u;
    TFR(17) TFR(29) TFR(16) TFR(24)
    x0 += K1; x1 += K2 + 4u;
    TFR(13) TFR(15) TFR(26) TFR(6)
    x0 += K2; x1 += K0 + 5u;
#undef TFR
    return x0 ^ x1;
}

// Exact JAX gumbel+score value (precise libdevice logf) — final arbiter only.
__device__ __forceinline__ float precise_v(unsigned ctr, float rowk) {
    unsigned b = tf_xor(ctr);
    float f = __uint_as_float((b >> 9) | 0x3f800000u) - 1.0f;
    float u = fmaxf(f, 1.17549435e-38f);
    return -logf(-logf(u)) + rowk;
}

// ---------------- K1: atomic-free partials of x @ W1 -------------------------
// 512 blocks x 256 threads; block b covers input rows [b*32, b*32+32)
__global__ void k_h_partial(const float* __restrict__ x, const float* __restrict__ W1) {
    __shared__ float sm[256];
    int t = threadIdx.x;
    int j = t & 127;
    int half = t >> 7;
    int i0 = blockIdx.x * 32 + half * 16;
    float acc = 0.0f;
#pragma unroll
    for (int ii = 0; ii < 16; ii++) {
        int i = i0 + ii;
        acc = fmaf(x[i], W1[i * HID + j], acc);
    }
    sm[t] = acc;
    __syncthreads();
    if (t < 128) g_hpart[blockIdx.x][j] = sm[t] + sm[t + 128];
}

// ---------------- K2: reduce partials -> hs; zero log_softmax ----------------
// 512 threads: 4 summers per column, smem combine.
__global__ void k_hsum(const float* __restrict__ b1, float* __restrict__ out) {
    __shared__ float sm[512];
    int t = threadIdx.x;
    int j = t & 127;
    int q = t >> 7;          // 0..3, sums blocks [q*128, q*128+128)
    float s = 0.0f;
#pragma unroll 8
    for (int b = 0; b < NPART / 4; b++) s += g_hpart[q * (NPART / 4) + b][j];
    sm[t] = s;
    __syncthreads();
    if (t < 128) {
        float tot = b1[j] + ((sm[j] + sm[j + 128]) + (sm[j + 256] + sm[j + 384]));
        g_hs[j] = tanh_xla(tot);
        out[OFF_LOGSM + j] = 0.0f;
    }
}

// ---------------- K3 fused: scores + rowstats + gumbel sampling --------------
// block = node n (2000 blocks x 128 threads); thread t = sample s in sampling phase
__global__ void __launch_bounds__(128) k_fused(const float* __restrict__ W2,
                                               const float* __restrict__ b2,
                                               float* __restrict__ out) {
    __shared__ float hs[HID];
    __shared__ float srow[SEG];
    __shared__ float red[8];
    __shared__ float sstat[2];    // rowmax, log(sumexp)
    const int n = blockIdx.x;
    const int t = threadIdx.x;
    const float NEGINF = -__int_as_float(0x7f800000);

    hs[t] = g_hs[t];
    __syncthreads();

    // --- scores for this node's 100 columns (coalesced over t) ---
    if (t < SEG) {
        int col = n * SEG + t;
        float acc = b2[col];
#pragma unroll 8
        for (int k = 0; k < HID; k++)
            acc = fmaf(hs[k], W2[(size_t)k * ALLN + col], acc);
        float sc = 10.0f * tanh_xla(acc);
        srow[t] = sc;
        out[OFF_SCORES + col] = sc;
    }
    __syncthreads();

    // --- in-block rowmax ---
    float v = (t < SEG) ? srow[t] : NEGINF;
#pragma unroll
    for (int off = 16; off > 0; off >>= 1)
        v = fmaxf(v, __shfl_xor_sync(0xffffffffu, v, off));
    if ((t & 31) == 0) red[t >> 5] = v;
    __syncthreads();
    if (t == 0) sstat[0] = fmaxf(fmaxf(red[0], red[1]), fmaxf(red[2], red[3]));
    __syncthreads();

    // --- in-block log(sum(exp(x - max))) ---
    float e = (t < SEG) ? expf(srow[t] - sstat[0]) : 0.0f;
#pragma unroll
    for (int off = 16; off > 0; off >>= 1)
        e += __shfl_xor_sync(0xffffffffu, e, off);
    if ((t & 31) == 0) red[4 + (t >> 5)] = e;
    __syncthreads();
    if (t == 0) sstat[1] = logf((red[4] + red[5]) + (red[6] + red[7]));
    __syncthreads();

    // --- sampling: thread t = sample s ---
    // Fast rank: v = -__logf(-__logf(u)) + srow[k]  (2 MUFU logs, ~2e-5 abs err
    // at the winner); track top-2; arbitrate with the exact JAX expression.
    unsigned base = (unsigned)t * (unsigned)(NODES * SEG) + (unsigned)n * (unsigned)SEG;
    float best = NEGINF, v2nd = NEGINF;
    int bk = 0, k2 = 0;
#pragma unroll 4
    for (int k = 0; k < SEG; k++) {
        unsigned b = tf_xor(base + (unsigned)k);
        float f = __uint_as_float((b >> 9) | 0x3f800000u) - 1.0f;
        float u = fmaxf(f, 1.17549435e-38f);
        float nl = -__logf(u);                 // fast MUFU log, > 0
        float v = -__logf(nl) + srow[k];       // fast MUFU log
        if (v > best) { v2nd = best; k2 = bk; best = v; bk = k; }
        else if (v > v2nd) { v2nd = v; k2 = k; }
    }
    // precise arbitration between the two fast candidates (tie -> smaller k)
    float p1 = precise_v(base + (unsigned)bk, srow[bk]);
    float p2 = precise_v(base + (unsigned)k2, srow[k2]);
    if (p2 > p1 || (p2 == p1 && k2 < bk)) bk = k2;

    out[t * NODES + n] = (float)bk;
    float lp = (srow[bk] - sstat[0]) - sstat[1];
    atomicAdd(&out[OFF_LOGSM + t], lp);
}

// ---------------- launch ----------------
extern "C" void kernel_launch(void* const* d_in, const int* in_sizes, int n_in,
                              void* d_out, int out_size) {
    const float* x  = (const float*)d_in[0];
    const float* W1 = (const float*)d_in[1];
    const float* b1 = (const float*)d_in[2];
    const float* W2 = (const float*)d_in[3];
    const float* b2 = (const float*)d_in[4];
    float* out = (float*)d_out;

    k_h_partial<<<NPART, 256>>>(x, W1);
    k_hsum<<<1, 512>>>(b1, out);
    k_fused<<<NODES, 128>>>(W2, b2, out);
}